// round 13
// baseline (speedup 1.0000x reference)
#include <cuda_runtime.h>
#include <cuda_fp16.h>
#include <cstdint>

#define B_ 64
#define S_ 2048
#define D_ 512
#define U_ 512
#define M_TOT (B_ * S_)
#define MB_CNT (M_TOT / 32)   // 4096 m32-blocks
#define STAGES 4              // k32 per stage (B ring), 16 stages total

// ---------------- scratch (__device__ globals: allocation-free rule) ----------
__device__ float g_hd[B_ * U_];
__device__ float g_scores[M_TOT];
__device__ float g_max[B_];
__device__ float g_invsum[B_];
__device__ float g_spart[4 * M_TOT];
__device__ float g_ctxp[(size_t)MB_CNT * D_];      // per-mb context partials (8MB)
__device__ uint4 g_encfrag[(size_t)MB_CNT * 2048]; // [mb][k16(32)][g(2)][lane(32)]
__device__ uint4 g_w1frag[8 * 4096];               // [nb][k16(32)][g(4)][lane(32)]

// ---------------- helpers ----------------------------------------------------
__device__ __forceinline__ uint32_t smem_u32(const void* p) {
    uint32_t a;
    asm("{ .reg .u64 t; cvta.to.shared.u64 t, %1; cvt.u32.u64 %0, t; }" : "=r"(a) : "l"(p));
    return a;
}
__device__ __forceinline__ void cp16(uint32_t dst, const void* src) {
    asm volatile("cp.async.cg.shared.global [%0], [%1], 16;" :: "r"(dst), "l"(src) : "memory");
}
#define CP_COMMIT() asm volatile("cp.async.commit_group;" ::: "memory")
#define CP_WAIT2()  asm volatile("cp.async.wait_group 2;" ::: "memory")
__device__ __forceinline__ void ldsm4(uint32_t r[4], uint32_t addr) {
    asm volatile("ldmatrix.sync.aligned.m8n8.x4.shared.b16 {%0,%1,%2,%3}, [%4];"
                 : "=r"(r[0]), "=r"(r[1]), "=r"(r[2]), "=r"(r[3]) : "r"(addr));
}
__device__ __forceinline__ void mma16816(float c[4], const uint32_t* a, const uint32_t* b) {
    asm volatile(
        "mma.sync.aligned.m16n8k16.row.col.f32.f16.f16.f32 "
        "{%0,%1,%2,%3}, {%4,%5,%6,%7}, {%8,%9}, {%0,%1,%2,%3};"
        : "+f"(c[0]), "+f"(c[1]), "+f"(c[2]), "+f"(c[3])
        : "r"(a[0]), "r"(a[1]), "r"(a[2]), "r"(a[3]), "r"(b[0]), "r"(b[1]));
}
__device__ __forceinline__ uint32_t h2u(half2 h) { return *reinterpret_cast<uint32_t*>(&h); }

// ---------------- fused prep: W1 fragments (bid 0-7) + decoder proj (bid 8-15)
#define WT_STRIDE 520
#define WT_SMEM (64 * WT_STRIDE * 2)

__global__ __launch_bounds__(256)
void prep_kernel(const float* __restrict__ W1,
                 const float* __restrict__ dec,
                 const float* __restrict__ W2,
                 const float* __restrict__ b2) {
    extern __shared__ __align__(16) char smem[];
    const int tid = threadIdx.x, lane = tid & 31, wid = tid >> 5;

    if (blockIdx.x < 8) {
        // ---- W1 transpose + f16 + fragment extract ----
        __half* swt = (__half*)smem;
        const int nb = blockIdx.x;
        const int nl = tid & 63, kg = tid >> 6;
        for (int i = 0; i < 128; i++) {
            const int k = kg * 128 + i;
            swt[nl * WT_STRIDE + k] = __float2half_rn(W1[(size_t)k * U_ + nb * 64 + nl]);
        }
        __syncthreads();
        const uint32_t base = smem_u32(swt);
        const uint32_t boff = ((lane & 7) + ((lane >> 4) & 1) * 8) * (WT_STRIDE * 2)
                            + ((lane >> 3) & 1) * 16;
#pragma unroll
        for (int t = 0; t < 2; t++) {
            const int kt = wid * 2 + t;
#pragma unroll
            for (int s = 0; s < 2; s++) {
                const int k16 = kt * 2 + s;
#pragma unroll
                for (int g = 0; g < 4; g++) {
                    uint32_t r[4];
                    ldsm4(r, base + g * 16 * (WT_STRIDE * 2) + k16 * 32 + boff);
                    g_w1frag[((nb * 32 + k16) * 4 + g) * 32 + lane] =
                        make_uint4(r[0], r[1], r[2], r[3]);
                }
            }
        }
    } else {
        // ---- decoder projection: 8 batches per CTA, 2 u per thread ----
        float* ds = (float*)smem;                 // [8][512]
        const int b0 = (blockIdx.x - 8) * 8;
#pragma unroll
        for (int j = 0; j < 16; j++)
            ds[tid + j * 256] = dec[b0 * D_ + tid + j * 256];
        __syncthreads();
        const int u0 = tid, u1 = tid + 256;
        float acc0[8], acc1[8];
#pragma unroll
        for (int b = 0; b < 8; b++) { acc0[b] = b2[u0]; acc1[b] = b2[u1]; }
        for (int k = 0; k < D_; k++) {
            const float w0 = W2[(size_t)k * U_ + u0];
            const float w1 = W2[(size_t)k * U_ + u1];
#pragma unroll
            for (int b = 0; b < 8; b++) {
                const float d = ds[b * D_ + k];
                acc0[b] = fmaf(d, w0, acc0[b]);
                acc1[b] = fmaf(d, w1, acc1[b]);
            }
        }
#pragma unroll
        for (int b = 0; b < 8; b++) {
            g_hd[(b0 + b) * U_ + u0] = acc0[b];
            g_hd[(b0 + b) * U_ + u1] = acc1[b];
        }
    }
}

// ---------------- prepass: enc f32 -> A fragments (f16), split grid ----------
__global__ __launch_bounds__(256)
void encfrag_kernel(const float* __restrict__ enc, int mb0) {
    __shared__ __align__(16) char sA[8][32 * 80];
    const int lane = threadIdx.x & 31, wid = threadIdx.x >> 5;
    const int mb = mb0 + blockIdx.x * 8 + wid;
    const float* src = enc + (size_t)mb * 32 * D_;
    char* ws = sA[wid];
    const uint32_t base = smem_u32(ws);
    const uint32_t aoff = ((lane & 7) + ((lane >> 3) & 1) * 8) * 80 + ((lane >> 4) & 1) * 16;
    const int r0 = lane >> 3;
    const int c0 = (lane & 7) * 4;

    for (int kt = 0; kt < 16; kt++) {
        const int k0 = kt * 32;
#pragma unroll
        for (int i = 0; i < 8; i++) {
            const int row = r0 + i * 4;
            float4 f = *(const float4*)(src + (size_t)row * D_ + k0 + c0);
            half2 h0 = __floats2half2_rn(f.x, f.y);
            half2 h1 = __floats2half2_rn(f.z, f.w);
            *(uint2*)(ws + row * 80 + c0 * 2) = make_uint2(h2u(h0), h2u(h1));
        }
        __syncwarp();
#pragma unroll
        for (int s = 0; s < 2; s++)
#pragma unroll
            for (int g = 0; g < 2; g++) {
                uint32_t r[4];
                ldsm4(r, base + g * 16 * 80 + s * 32 + aoff);
                g_encfrag[(((size_t)mb * 32 + kt * 2 + s) * 2 + g) * 32 + lane] =
                    make_uint4(r[0], r[1], r[2], r[3]);
            }
        __syncwarp();
    }
}

// ---------------- main score kernel: B smem ring, A direct LDG ---------------
#define STG_U4 512
#define SMEM_STG_BYTES (STAGES * STG_U4 * 16)  // 32768
#define SMEM_DYN_TOTAL (SMEM_STG_BYTES + 3 * 128 * 4)

__global__ __launch_bounds__(256, 2)
void score_pipe_kernel(const float* __restrict__ b1, const float* __restrict__ V) {
    extern __shared__ __align__(16) char smem[];
    uint4* stg = (uint4*)smem;
    float* cpre = (float*)(smem + SMEM_STG_BYTES);
    float* vpre = cpre + 128;
    float* ssum = vpre + 128;

    const int tid = threadIdx.x, lane = tid & 31, wid = tid >> 5;
    const int wm = wid >> 1, wn = wid & 1;
    const int n0 = blockIdx.x * 128, m0 = blockIdx.y * 128, b = m0 >> 11;

    if (tid < 128) {
        cpre[tid] = b1[n0 + tid] + g_hd[b * U_ + n0 + tid];
        vpre[tid] = V[n0 + tid];
        ssum[tid] = 0.0f;
    }

    const uint4* bsrc = g_w1frag +
        (((size_t)(blockIdx.x * 2 + (tid >> 7)) * 32) * 4 + ((tid >> 5) & 3)) * 32 + (tid & 31);
    const uint4* Ap = g_encfrag + (size_t)(blockIdx.y * 4 + wm) * 2048 + lane;

#pragma unroll
    for (int s = 0; s < 3; s++) {
        uint4* sp = stg + s * STG_U4;
        cp16(smem_u32(sp + tid),       bsrc + (size_t)(2 * s) * 128);
        cp16(smem_u32(sp + 256 + tid), bsrc + (size_t)(2 * s + 1) * 128);
        CP_COMMIT();
    }

    uint4 a00 = Ap[0],  a01 = Ap[32];
    uint4 a10 = Ap[64], a11 = Ap[96];

    float acc[2][8][4] = {};
    const int boff = wn * 128 + lane;

    int buf = 0, pbuf = 3;
#pragma unroll 4
    for (int st = 0; st < 16; st++) {
        CP_WAIT2();
        __syncthreads();

        if (st + 3 < 16) {
            uint4* sp = stg + pbuf * STG_U4;
            cp16(smem_u32(sp + tid),       bsrc + (size_t)(2 * (st + 3)) * 128);
            cp16(smem_u32(sp + 256 + tid), bsrc + (size_t)(2 * (st + 3) + 1) * 128);
        }
        CP_COMMIT();

        const uint4* sb = stg + buf * STG_U4;

        {  // sub 0
            uint4 f0 = sb[boff], f1 = sb[boff + 32], f2 = sb[boff + 64], f3 = sb[boff + 96];
            const uint32_t* A0 = (const uint32_t*)&a00;
            const uint32_t* A1 = (const uint32_t*)&a01;
            const uint32_t* B0 = (const uint32_t*)&f0;
            const uint32_t* B1 = (const uint32_t*)&f1;
            const uint32_t* B2 = (const uint32_t*)&f2;
            const uint32_t* B3 = (const uint32_t*)&f3;
            mma16816(acc[0][0], A0, B0); mma16816(acc[0][1], A0, B0 + 2);
            mma16816(acc[1][0], A1, B0); mma16816(acc[1][1], A1, B0 + 2);
            mma16816(acc[0][2], A0, B1); mma16816(acc[0][3], A0, B1 + 2);
            mma16816(acc[1][2], A1, B1); mma16816(acc[1][3], A1, B1 + 2);
            mma16816(acc[0][4], A0, B2); mma16816(acc[0][5], A0, B2 + 2);
            mma16816(acc[1][4], A1, B2); mma16816(acc[1][5], A1, B2 + 2);
            mma16816(acc[0][6], A0, B3); mma16816(acc[0][7], A0, B3 + 2);
            mma16816(acc[1][6], A1, B3); mma16816(acc[1][7], A1, B3 + 2);
        }
        if (st < 15) {
            a00 = Ap[(size_t)(2 * st + 2) * 64];
            a01 = Ap[(size_t)(2 * st + 2) * 64 + 32];
        }

        {  // sub 1
            const uint4* sb1 = sb + 256;
            uint4 f0 = sb1[boff], f1 = sb1[boff + 32], f2 = sb1[boff + 64], f3 = sb1[boff + 96];
            const uint32_t* A0 = (const uint32_t*)&a10;
            const uint32_t* A1 = (const uint32_t*)&a11;
            const uint32_t* B0 = (const uint32_t*)&f0;
            const uint32_t* B1 = (const uint32_t*)&f1;
            const uint32_t* B2 = (const uint32_t*)&f2;
            const uint32_t* B3 = (const uint32_t*)&f3;
            mma16816(acc[0][0], A0, B0); mma16816(acc[0][1], A0, B0 + 2);
            mma16816(acc[1][0], A1, B0); mma16816(acc[1][1], A1, B0 + 2);
            mma16816(acc[0][2], A0, B1); mma16816(acc[0][3], A0, B1 + 2);
            mma16816(acc[1][2], A1, B1); mma16816(acc[1][3], A1, B1 + 2);
            mma16816(acc[0][4], A0, B2); mma16816(acc[0][5], A0, B2 + 2);
            mma16816(acc[1][4], A1, B2); mma16816(acc[1][5], A1, B2 + 2);
            mma16816(acc[0][6], A0, B3); mma16816(acc[0][7], A0, B3 + 2);
            mma16816(acc[1][6], A1, B3); mma16816(acc[1][7], A1, B3 + 2);
        }
        if (st < 15) {
            a10 = Ap[(size_t)(2 * st + 3) * 64];
            a11 = Ap[(size_t)(2 * st + 3) * 64 + 32];
        }

        buf = (buf + 1) & 3;
        pbuf = (pbuf + 1) & 3;
    }

    __syncthreads();

    const int g = lane >> 2, tg = lane & 3;
    const int n_base = wn * 64;
    float p[2][2] = {{0.0f, 0.0f}, {0.0f, 0.0f}};
#pragma unroll
    for (int mf = 0; mf < 2; mf++) {
#pragma unroll
        for (int nf = 0; nf < 8; nf++) {
            const int c0 = n_base + nf * 8 + tg * 2;
            const float v0 = vpre[c0], v1 = vpre[c0 + 1];
            const float k0 = cpre[c0], k1 = cpre[c0 + 1];
            p[mf][0] += v0 * tanhf(acc[mf][nf][0] + k0) + v1 * tanhf(acc[mf][nf][1] + k1);
            p[mf][1] += v0 * tanhf(acc[mf][nf][2] + k0) + v1 * tanhf(acc[mf][nf][3] + k1);
        }
    }
#pragma unroll
    for (int mf = 0; mf < 2; mf++)
#pragma unroll
        for (int h = 0; h < 2; h++) {
            float s = p[mf][h];
            s += __shfl_xor_sync(0xffffffffu, s, 1);
            s += __shfl_xor_sync(0xffffffffu, s, 2);
            if (tg == 0) atomicAdd(&ssum[wm * 32 + mf * 16 + h * 8 + g], s);
        }
    __syncthreads();
    if (tid < 128) g_spart[(size_t)blockIdx.x * M_TOT + m0 + tid] = ssum[tid];
}

// ---------------- softmax stats (512 threads) --------------------------------
__global__ __launch_bounds__(512)
void stats_kernel() {
    const int b = blockIdx.x;
    const int tid = threadIdx.x;  // 512
    __shared__ float red[512];
    float m = -1e30f;
    for (int s = tid; s < S_; s += 512) {
        const int i = b * S_ + s;
        const float v = g_spart[i] + g_spart[M_TOT + i] + g_spart[2 * M_TOT + i] + g_spart[3 * M_TOT + i];
        g_scores[i] = v;
        m = fmaxf(m, v);
    }
    red[tid] = m;
    __syncthreads();
    for (int o = 256; o; o >>= 1) {
        if (tid < o) red[tid] = fmaxf(red[tid], red[tid + o]);
        __syncthreads();
    }
    const float mx = red[0];
    __syncthreads();
    float sum = 0.0f;
    for (int s = tid; s < S_; s += 512) sum += expf(g_scores[b * S_ + s] - mx);
    red[tid] = sum;
    __syncthreads();
    for (int o = 256; o; o >>= 1) {
        if (tid < o) red[tid] += red[tid + o];
        __syncthreads();
    }
    if (tid == 0) {
        g_max[b] = mx;
        g_invsum[b] = 1.0f / red[0];
    }
}

// ---------------- context from f16 A-fragments -------------------------------
__global__ __launch_bounds__(128)
void cpart_kernel() {
    const int lane = threadIdx.x & 31, w = threadIdx.x >> 5;
    const int b = blockIdx.y;
    const int mbl = blockIdx.x * 4 + w;
    const int mb = b * 64 + mbl;
    const float mx = g_max[b], inv = g_invsum[b];
    const float* sc = g_scores + b * S_ + mbl * 32;
    const int rq = lane >> 2;
    const float wa0 = expf(sc[rq] - mx) * inv;
    const float wb0 = expf(sc[rq + 8] - mx) * inv;
    const float wa1 = expf(sc[rq + 16] - mx) * inv;
    const float wb1 = expf(sc[rq + 24] - mx) * inv;

    const uint4* src = g_encfrag + (size_t)mb * 2048 + lane;
    float* dst = g_ctxp + (size_t)mb * D_;

#pragma unroll 4
    for (int k = 0; k < 32; k++) {
        const uint4 f0 = src[(size_t)k * 64];
        const uint4 f1 = src[(size_t)k * 64 + 32];
        float2 v;
        float a0, a1, a8, a9;
        v = __half22float2(*(const half2*)&f0.x); a0 = wa0 * v.x; a1 = wa0 * v.y;
        v = __half22float2(*(const half2*)&f0.y); a0 = fmaf(wb0, v.x, a0); a1 = fmaf(wb0, v.y, a1);
        v = __half22float2(*(const half2*)&f0.z); a8 = wa0 * v.x; a9 = wa0 * v.y;
        v = __half22float2(*(const half2*)&f0.w); a8 = fmaf(wb0, v.x, a8); a9 = fmaf(wb0, v.y, a9);
        v = __half22float2(*(const half2*)&f1.x); a0 = fmaf(wa1, v.x, a0); a1 = fmaf(wa1, v.y, a1);
        v = __half22float2(*(const half2*)&f1.y); a0 = fmaf(wb1, v.x, a0); a1 = fmaf(wb1, v.y, a1);
        v = __half22float2(*(const half2*)&f1.z); a8 = fmaf(wa1, v.x, a8); a9 = fmaf(wa1, v.y, a9);
        v = __half22float2(*(const half2*)&f1.w); a8 = fmaf(wb1, v.x, a8); a9 = fmaf(wb1, v.y, a9);
#pragma unroll
        for (int o = 4; o <= 16; o <<= 1) {
            a0 += __shfl_xor_sync(0xffffffffu, a0, o);
            a1 += __shfl_xor_sync(0xffffffffu, a1, o);
            a8 += __shfl_xor_sync(0xffffffffu, a8, o);
            a9 += __shfl_xor_sync(0xffffffffu, a9, o);
        }
        if (lane < 4) {
            float2* d = (float2*)(dst + k * 16);
            d[lane] = make_float2(a0, a1);
            d[lane + 4] = make_float2(a8, a9);
        }
    }
}

__global__ void cfinal_kernel(float* __restrict__ out) {
    const int b = blockIdx.x;
    const int tid = threadIdx.x;    // 128
    float4 acc = make_float4(0.f, 0.f, 0.f, 0.f);
    const float4* p = (const float4*)(g_ctxp + (size_t)b * 64 * D_) + tid;
#pragma unroll
    for (int j = 0; j < 64; j++) {
        const float4 v = p[(size_t)j * 128];
        acc.x += v.x; acc.y += v.y; acc.z += v.z; acc.w += v.w;
    }
    ((float4*)out)[b * 128 + tid] = acc;
}

// ---------------- launch ------------------------------------------------------
extern "C" void kernel_launch(void* const* d_in, const int* in_sizes, int n_in,
                              void* d_out, int out_size) {
    const float* enc = (const float*)d_in[0];
    const float* dec = (const float*)d_in[1];
    const float* W1  = (const float*)d_in[2];
    const float* b1  = (const float*)d_in[3];
    const float* W2  = (const float*)d_in[4];
    const float* b2  = (const float*)d_in[5];
    const float* V   = (const float*)d_in[6];
    // d_in[7] = bv: constant shift, cancels in softmax.
    float* out = (float*)d_out;

    cudaFuncSetAttribute(score_pipe_kernel,
                         cudaFuncAttributeMaxDynamicSharedMemorySize, SMEM_DYN_TOTAL);
    cudaFuncSetAttribute(prep_kernel,
                         cudaFuncAttributeMaxDynamicSharedMemorySize, WT_SMEM);

    prep_kernel<<<16, 256, WT_SMEM>>>(W1, dec, W2, b2);                      // idx 0
    encfrag_kernel<<<MB_CNT / 16, 256>>>(enc, 0);                            // idx 1
    encfrag_kernel<<<MB_CNT / 16, 256>>>(enc, MB_CNT / 2);                   // idx 2
    score_pipe_kernel<<<dim3(4, M_TOT / 128), 256, SMEM_DYN_TOTAL>>>(b1, V); // idx 3 (profiled)
    stats_kernel<<<B_, 512>>>();                                             // idx 4
    cpart_kernel<<<dim3(16, B_), 128>>>();                                   // idx 5
    cfinal_kernel<<<B_, 128>>>(out);                                         // idx 6
}

// round 14
// speedup vs baseline: 1.2456x; 1.2456x over previous
#include <cuda_runtime.h>
#include <cuda_fp16.h>
#include <cstdint>

#define B_ 64
#define S_ 2048
#define D_ 512
#define U_ 512
#define M_TOT (B_ * S_)
#define MB_CNT (M_TOT / 32)   // 4096 m32-blocks
#define STAGES 4              // k32 per stage (B ring), 16 stages total

// ---------------- scratch (__device__ globals: allocation-free rule) ----------
__device__ float g_hd[B_ * U_];
__device__ float g_scores[M_TOT];
__device__ float g_max[B_];
__device__ float g_invsum[B_];
__device__ float g_spart[4 * M_TOT];
__device__ float g_ctxp[(size_t)MB_CNT * D_];      // per-mb context partials (8MB)
__device__ uint4 g_encfrag[(size_t)MB_CNT * 2048]; // [mb][k16(32)][g(2)][lane(32)]
__device__ uint4 g_w1frag[8 * 4096];               // [nb][k16(32)][g(4)][lane(32)]

// ---------------- helpers ----------------------------------------------------
__device__ __forceinline__ uint32_t smem_u32(const void* p) {
    uint32_t a;
    asm("{ .reg .u64 t; cvta.to.shared.u64 t, %1; cvt.u32.u64 %0, t; }" : "=r"(a) : "l"(p));
    return a;
}
__device__ __forceinline__ void cp16(uint32_t dst, const void* src) {
    asm volatile("cp.async.cg.shared.global [%0], [%1], 16;" :: "r"(dst), "l"(src) : "memory");
}
#define CP_COMMIT() asm volatile("cp.async.commit_group;" ::: "memory")
#define CP_WAIT2()  asm volatile("cp.async.wait_group 2;" ::: "memory")
__device__ __forceinline__ void ldsm4(uint32_t r[4], uint32_t addr) {
    asm volatile("ldmatrix.sync.aligned.m8n8.x4.shared.b16 {%0,%1,%2,%3}, [%4];"
                 : "=r"(r[0]), "=r"(r[1]), "=r"(r[2]), "=r"(r[3]) : "r"(addr));
}
__device__ __forceinline__ void mma16816(float c[4], const uint32_t* a, const uint32_t* b) {
    asm volatile(
        "mma.sync.aligned.m16n8k16.row.col.f32.f16.f16.f32 "
        "{%0,%1,%2,%3}, {%4,%5,%6,%7}, {%8,%9}, {%0,%1,%2,%3};"
        : "+f"(c[0]), "+f"(c[1]), "+f"(c[2]), "+f"(c[3])
        : "r"(a[0]), "r"(a[1]), "r"(a[2]), "r"(a[3]), "r"(b[0]), "r"(b[1]));
}
__device__ __forceinline__ uint32_t h2u(half2 h) { return *reinterpret_cast<uint32_t*>(&h); }

// ---------------- W1 prepass: transpose + f16 + fragment extract -------------
#define WT_STRIDE 520
#define WT_SMEM (64 * WT_STRIDE * 2)

__global__ __launch_bounds__(256)
void wfrag_kernel(const float* __restrict__ W1) {
    extern __shared__ __align__(16) char smem[];
    __half* swt = (__half*)smem;
    const int tid = threadIdx.x, lane = tid & 31, wid = tid >> 5;
    const int nb = blockIdx.x;
    const int nl = tid & 63, kg = tid >> 6;

    for (int i = 0; i < 128; i++) {
        const int k = kg * 128 + i;
        swt[nl * WT_STRIDE + k] = __float2half_rn(W1[(size_t)k * U_ + nb * 64 + nl]);
    }
    __syncthreads();

    const uint32_t base = smem_u32(swt);
    const uint32_t boff = ((lane & 7) + ((lane >> 4) & 1) * 8) * (WT_STRIDE * 2)
                        + ((lane >> 3) & 1) * 16;
#pragma unroll
    for (int t = 0; t < 2; t++) {
        const int kt = wid * 2 + t;
#pragma unroll
        for (int s = 0; s < 2; s++) {
            const int k16 = kt * 2 + s;
#pragma unroll
            for (int g = 0; g < 4; g++) {
                uint32_t r[4];
                ldsm4(r, base + g * 16 * (WT_STRIDE * 2) + k16 * 32 + boff);
                g_w1frag[((nb * 32 + k16) * 4 + g) * 32 + lane] =
                    make_uint4(r[0], r[1], r[2], r[3]);
            }
        }
    }
}

// ---------------- prepass: enc f32 -> A fragments (f16) ----------------------
__global__ __launch_bounds__(256)
void encfrag_kernel(const float* __restrict__ enc) {
    __shared__ __align__(16) char sA[8][32 * 80];
    const int lane = threadIdx.x & 31, wid = threadIdx.x >> 5;
    const int mb = blockIdx.x * 8 + wid;
    const float* src = enc + (size_t)mb * 32 * D_;
    char* ws = sA[wid];
    const uint32_t base = smem_u32(ws);
    const uint32_t aoff = ((lane & 7) + ((lane >> 3) & 1) * 8) * 80 + ((lane >> 4) & 1) * 16;
    const int r0 = lane >> 3;
    const int c0 = (lane & 7) * 4;

    for (int kt = 0; kt < 16; kt++) {
        const int k0 = kt * 32;
#pragma unroll
        for (int i = 0; i < 8; i++) {
            const int row = r0 + i * 4;
            float4 f = *(const float4*)(src + (size_t)row * D_ + k0 + c0);
            half2 h0 = __floats2half2_rn(f.x, f.y);
            half2 h1 = __floats2half2_rn(f.z, f.w);
            *(uint2*)(ws + row * 80 + c0 * 2) = make_uint2(h2u(h0), h2u(h1));
        }
        __syncwarp();
#pragma unroll
        for (int s = 0; s < 2; s++)
#pragma unroll
            for (int g = 0; g < 2; g++) {
                uint32_t r[4];
                ldsm4(r, base + g * 16 * 80 + s * 32 + aoff);
                g_encfrag[(((size_t)mb * 32 + kt * 2 + s) * 2 + g) * 32 + lane] =
                    make_uint4(r[0], r[1], r[2], r[3]);
            }
        __syncwarp();
    }
}

__global__ void hd_kernel(const float* __restrict__ dec,
                          const float* __restrict__ W2,
                          const float* __restrict__ b2) {
    __shared__ float ds[D_];
    int b = blockIdx.x;
    int u = threadIdx.x;
    ds[u] = dec[b * D_ + u];
    __syncthreads();
    float a = b2[u];
#pragma unroll 8
    for (int k = 0; k < D_; k++) a = fmaf(ds[k], W2[k * U_ + u], a);
    g_hd[b * U_ + u] = a;
}

// ---------------- main score kernel: B smem ring, A direct LDG ---------------
#define STG_U4 512
#define SMEM_STG_BYTES (STAGES * STG_U4 * 16)  // 32768
#define SMEM_DYN_TOTAL (SMEM_STG_BYTES + 3 * 128 * 4)

__global__ __launch_bounds__(256, 2)
void score_pipe_kernel(const float* __restrict__ b1, const float* __restrict__ V) {
    extern __shared__ __align__(16) char smem[];
    uint4* stg = (uint4*)smem;
    float* cpre = (float*)(smem + SMEM_STG_BYTES);
    float* vpre = cpre + 128;
    float* ssum = vpre + 128;

    const int tid = threadIdx.x, lane = tid & 31, wid = tid >> 5;
    const int wm = wid >> 1, wn = wid & 1;
    const int n0 = blockIdx.x * 128, m0 = blockIdx.y * 128, b = m0 >> 11;

    if (tid < 128) {
        cpre[tid] = b1[n0 + tid] + g_hd[b * U_ + n0 + tid];
        vpre[tid] = V[n0 + tid];
        ssum[tid] = 0.0f;
    }

    const uint4* bsrc = g_w1frag +
        (((size_t)(blockIdx.x * 2 + (tid >> 7)) * 32) * 4 + ((tid >> 5) & 3)) * 32 + (tid & 31);
    const uint4* Ap = g_encfrag + (size_t)(blockIdx.y * 4 + wm) * 2048 + lane;

#pragma unroll
    for (int s = 0; s < 3; s++) {
        uint4* sp = stg + s * STG_U4;
        cp16(smem_u32(sp + tid),       bsrc + (size_t)(2 * s) * 128);
        cp16(smem_u32(sp + 256 + tid), bsrc + (size_t)(2 * s + 1) * 128);
        CP_COMMIT();
    }

    uint4 a00 = Ap[0],  a01 = Ap[32];
    uint4 a10 = Ap[64], a11 = Ap[96];

    float acc[2][8][4] = {};
    const int boff = wn * 128 + lane;

    int buf = 0, pbuf = 3;
#pragma unroll
    for (int st = 0; st < 16; st++) {
        CP_WAIT2();
        __syncthreads();

        if (st + 3 < 16) {
            uint4* sp = stg + pbuf * STG_U4;
            cp16(smem_u32(sp + tid),       bsrc + (size_t)(2 * (st + 3)) * 128);
            cp16(smem_u32(sp + 256 + tid), bsrc + (size_t)(2 * (st + 3) + 1) * 128);
        }
        CP_COMMIT();

        const uint4* sb = stg + buf * STG_U4;

        {  // sub 0
            uint4 f0 = sb[boff], f1 = sb[boff + 32], f2 = sb[boff + 64], f3 = sb[boff + 96];
            const uint32_t* A0 = (const uint32_t*)&a00;
            const uint32_t* A1 = (const uint32_t*)&a01;
            const uint32_t* B0 = (const uint32_t*)&f0;
            const uint32_t* B1 = (const uint32_t*)&f1;
            const uint32_t* B2 = (const uint32_t*)&f2;
            const uint32_t* B3 = (const uint32_t*)&f3;
            mma16816(acc[0][0], A0, B0); mma16816(acc[0][1], A0, B0 + 2);
            mma16816(acc[1][0], A1, B0); mma16816(acc[1][1], A1, B0 + 2);
            mma16816(acc[0][2], A0, B1); mma16816(acc[0][3], A0, B1 + 2);
            mma16816(acc[1][2], A1, B1); mma16816(acc[1][3], A1, B1 + 2);
            mma16816(acc[0][4], A0, B2); mma16816(acc[0][5], A0, B2 + 2);
            mma16816(acc[1][4], A1, B2); mma16816(acc[1][5], A1, B2 + 2);
            mma16816(acc[0][6], A0, B3); mma16816(acc[0][7], A0, B3 + 2);
            mma16816(acc[1][6], A1, B3); mma16816(acc[1][7], A1, B3 + 2);
        }
        if (st < 15) {
            a00 = Ap[(size_t)(2 * st + 2) * 64];
            a01 = Ap[(size_t)(2 * st + 2) * 64 + 32];
        }

        {  // sub 1
            const uint4* sb1 = sb + 256;
            uint4 f0 = sb1[boff], f1 = sb1[boff + 32], f2 = sb1[boff + 64], f3 = sb1[boff + 96];
            const uint32_t* A0 = (const uint32_t*)&a10;
            const uint32_t* A1 = (const uint32_t*)&a11;
            const uint32_t* B0 = (const uint32_t*)&f0;
            const uint32_t* B1 = (const uint32_t*)&f1;
            const uint32_t* B2 = (const uint32_t*)&f2;
            const uint32_t* B3 = (const uint32_t*)&f3;
            mma16816(acc[0][0], A0, B0); mma16816(acc[0][1], A0, B0 + 2);
            mma16816(acc[1][0], A1, B0); mma16816(acc[1][1], A1, B0 + 2);
            mma16816(acc[0][2], A0, B1); mma16816(acc[0][3], A0, B1 + 2);
            mma16816(acc[1][2], A1, B1); mma16816(acc[1][3], A1, B1 + 2);
            mma16816(acc[0][4], A0, B2); mma16816(acc[0][5], A0, B2 + 2);
            mma16816(acc[1][4], A1, B2); mma16816(acc[1][5], A1, B2 + 2);
            mma16816(acc[0][6], A0, B3); mma16816(acc[0][7], A0, B3 + 2);
            mma16816(acc[1][6], A1, B3); mma16816(acc[1][7], A1, B3 + 2);
        }
        if (st < 15) {
            a10 = Ap[(size_t)(2 * st + 3) * 64];
            a11 = Ap[(size_t)(2 * st + 3) * 64 + 32];
        }

        buf = (buf + 1) & 3;
        pbuf = (pbuf + 1) & 3;
    }

    __syncthreads();

    const int g = lane >> 2, tg = lane & 3;
    const int n_base = wn * 64;
    float p[2][2] = {{0.0f, 0.0f}, {0.0f, 0.0f}};
#pragma unroll
    for (int mf = 0; mf < 2; mf++) {
#pragma unroll
        for (int nf = 0; nf < 8; nf++) {
            const int c0 = n_base + nf * 8 + tg * 2;
            const float v0 = vpre[c0], v1 = vpre[c0 + 1];
            const float k0 = cpre[c0], k1 = cpre[c0 + 1];
            p[mf][0] += v0 * tanhf(acc[mf][nf][0] + k0) + v1 * tanhf(acc[mf][nf][1] + k1);
            p[mf][1] += v0 * tanhf(acc[mf][nf][2] + k0) + v1 * tanhf(acc[mf][nf][3] + k1);
        }
    }
#pragma unroll
    for (int mf = 0; mf < 2; mf++)
#pragma unroll
        for (int h = 0; h < 2; h++) {
            float s = p[mf][h];
            s += __shfl_xor_sync(0xffffffffu, s, 1);
            s += __shfl_xor_sync(0xffffffffu, s, 2);
            if (tg == 0) atomicAdd(&ssum[wm * 32 + mf * 16 + h * 8 + g], s);
        }
    __syncthreads();
    if (tid < 128) g_spart[(size_t)blockIdx.x * M_TOT + m0 + tid] = ssum[tid];
}

// ---------------- softmax stats (512 threads) --------------------------------
__global__ __launch_bounds__(512)
void stats_kernel() {
    const int b = blockIdx.x;
    const int tid = threadIdx.x;  // 512
    __shared__ float red[512];
    float m = -1e30f;
    for (int s = tid; s < S_; s += 512) {
        const int i = b * S_ + s;
        const float v = g_spart[i] + g_spart[M_TOT + i] + g_spart[2 * M_TOT + i] + g_spart[3 * M_TOT + i];
        g_scores[i] = v;
        m = fmaxf(m, v);
    }
    red[tid] = m;
    __syncthreads();
    for (int o = 256; o; o >>= 1) {
        if (tid < o) red[tid] = fmaxf(red[tid], red[tid + o]);
        __syncthreads();
    }
    const float mx = red[0];
    __syncthreads();
    float sum = 0.0f;
    for (int s = tid; s < S_; s += 512) sum += expf(g_scores[b * S_ + s] - mx);
    red[tid] = sum;
    __syncthreads();
    for (int o = 256; o; o >>= 1) {
        if (tid < o) red[tid] += red[tid + o];
        __syncthreads();
    }
    if (tid == 0) {
        g_max[b] = mx;
        g_invsum[b] = 1.0f / red[0];
    }
}

// ---------------- context from f16 A-fragments -------------------------------
__global__ __launch_bounds__(128)
void cpart_kernel() {
    const int lane = threadIdx.x & 31, w = threadIdx.x >> 5;
    const int b = blockIdx.y;
    const int mbl = blockIdx.x * 4 + w;
    const int mb = b * 64 + mbl;
    const float mx = g_max[b], inv = g_invsum[b];
    const float* sc = g_scores + b * S_ + mbl * 32;
    const int rq = lane >> 2;
    const float wa0 = expf(sc[rq] - mx) * inv;
    const float wb0 = expf(sc[rq + 8] - mx) * inv;
    const float wa1 = expf(sc[rq + 16] - mx) * inv;
    const float wb1 = expf(sc[rq + 24] - mx) * inv;

    const uint4* src = g_encfrag + (size_t)mb * 2048 + lane;
    float* dst = g_ctxp + (size_t)mb * D_;

#pragma unroll 4
    for (int k = 0; k < 32; k++) {
        const uint4 f0 = src[(size_t)k * 64];
        const uint4 f1 = src[(size_t)k * 64 + 32];
        float2 v;
        float a0, a1, a8, a9;
        v = __half22float2(*(const half2*)&f0.x); a0 = wa0 * v.x; a1 = wa0 * v.y;
        v = __half22float2(*(const half2*)&f0.y); a0 = fmaf(wb0, v.x, a0); a1 = fmaf(wb0, v.y, a1);
        v = __half22float2(*(const half2*)&f0.z); a8 = wa0 * v.x; a9 = wa0 * v.y;
        v = __half22float2(*(const half2*)&f0.w); a8 = fmaf(wb0, v.x, a8); a9 = fmaf(wb0, v.y, a9);
        v = __half22float2(*(const half2*)&f1.x); a0 = fmaf(wa1, v.x, a0); a1 = fmaf(wa1, v.y, a1);
        v = __half22float2(*(const half2*)&f1.y); a0 = fmaf(wb1, v.x, a0); a1 = fmaf(wb1, v.y, a1);
        v = __half22float2(*(const half2*)&f1.z); a8 = fmaf(wa1, v.x, a8); a9 = fmaf(wa1, v.y, a9);
        v = __half22float2(*(const half2*)&f1.w); a8 = fmaf(wb1, v.x, a8); a9 = fmaf(wb1, v.y, a9);
#pragma unroll
        for (int o = 4; o <= 16; o <<= 1) {
            a0 += __shfl_xor_sync(0xffffffffu, a0, o);
            a1 += __shfl_xor_sync(0xffffffffu, a1, o);
            a8 += __shfl_xor_sync(0xffffffffu, a8, o);
            a9 += __shfl_xor_sync(0xffffffffu, a9, o);
        }
        if (lane < 4) {
            float2* d = (float2*)(dst + k * 16);
            d[lane] = make_float2(a0, a1);
            d[lane + 4] = make_float2(a8, a9);
        }
    }
}

__global__ void cfinal_kernel(float* __restrict__ out) {
    const int b = blockIdx.x;
    const int tid = threadIdx.x;    // 128
    float4 acc = make_float4(0.f, 0.f, 0.f, 0.f);
    const float4* p = (const float4*)(g_ctxp + (size_t)b * 64 * D_) + tid;
#pragma unroll
    for (int j = 0; j < 64; j++) {
        const float4 v = p[(size_t)j * 128];
        acc.x += v.x; acc.y += v.y; acc.z += v.z; acc.w += v.w;
    }
    ((float4*)out)[b * 128 + tid] = acc;
}

// ---------------- launch ------------------------------------------------------
extern "C" void kernel_launch(void* const* d_in, const int* in_sizes, int n_in,
                              void* d_out, int out_size) {
    const float* enc = (const float*)d_in[0];
    const float* dec = (const float*)d_in[1];
    const float* W1  = (const float*)d_in[2];
    const float* b1  = (const float*)d_in[3];
    const float* W2  = (const float*)d_in[4];
    const float* b2  = (const float*)d_in[5];
    const float* V   = (const float*)d_in[6];
    // d_in[7] = bv: constant shift, cancels in softmax.
    float* out = (float*)d_out;

    cudaFuncSetAttribute(score_pipe_kernel,
                         cudaFuncAttributeMaxDynamicSharedMemorySize, SMEM_DYN_TOTAL);
    cudaFuncSetAttribute(wfrag_kernel,
                         cudaFuncAttributeMaxDynamicSharedMemorySize, WT_SMEM);

    wfrag_kernel<<<8, 256, WT_SMEM>>>(W1);                                   // idx 0
    encfrag_kernel<<<MB_CNT / 8, 256>>>(enc);                                // idx 1
    hd_kernel<<<B_, U_>>>(dec, W2, b2);                                      // idx 2
    score_pipe_kernel<<<dim3(4, M_TOT / 128), 256, SMEM_DYN_TOTAL>>>(b1, V); // idx 3 (profiled)
    stats_kernel<<<B_, 512>>>();                                             // idx 4
    cpart_kernel<<<dim3(16, B_), 128>>>();                                   // idx 5
    cfinal_kernel<<<B_, 128>>>(out);                                         // idx 6
}